// round 3
// baseline (speedup 1.0000x reference)
#include <cuda_runtime.h>
#include <math.h>

#define NN    96
#define INDIM 64
#define HID   256
#define ZDIM  64
#define TRIN  4656
#define GRIDN 96
#define NT    96
#define ITERS 50
#define MSLOT ((NN + 1) * NN)      // 97 rows of 96; row 96 = zero pad

// ------------- persistent device scratch (no allocations allowed) -------------
__device__ int   g_flag[GRIDN];     // per-block monotonic arrival counters
__device__ float g_norm[3];         // rotating norm^2 accumulators
__device__ int   g_cnt[NN * NN];
__device__ float g_dis[NN];
__device__ float g_degA[NN];
__device__ float g_tmp1[NN * HID];
__device__ float g_tmp2[NN * HID];
__device__ float g_h[NN * HID];
__device__ float g_gvec[HID];
__device__ float g_d1[HID];
__device__ float g_kl;
__device__ float g_vecb[TRIN];
__device__ float g_B[NN * NN];
__device__ float g_Bd[NN];
__device__ float g_degB[NN];
__device__ float g_recpart[NN];
__device__ float g_M[2 * MSLOT];    // ping-pong max-message matrix (+pad row)

// ---- flag-array grid barrier: no atomics, coalesced poll, monotonic across replays ----
struct Bar { int base; int ph; };

__device__ __forceinline__ void gsync(Bar& b) {
    __threadfence();                 // release: drain this thread's prior global stores
    __syncthreads();                 // all block threads' stores ordered before flag
    int tgt = b.base + (++b.ph);
    if (threadIdx.x == 0)
        asm volatile("st.global.cg.s32 [%0], %1;"
                     :: "l"(&g_flag[blockIdx.x]), "r"(tgt) : "memory");
    int ok;
    do {
        int v;
        asm volatile("ld.global.cg.s32 %0, [%1];"
                     : "=r"(v) : "l"(&g_flag[threadIdx.x]) : "memory");
        ok = __syncthreads_and(v >= tgt);
    } while (!ok);
    // consumers read cross-block data with __ldcg (L2) -> no acquire fence needed
}

__device__ __forceinline__ float blk_sum(float v, volatile float* s_w) {
    __syncthreads();
    #pragma unroll
    for (int o = 16; o; o >>= 1) v += __shfl_down_sync(0xFFFFFFFFu, v, o);
    if ((threadIdx.x & 31) == 0) s_w[threadIdx.x >> 5] = v;
    __syncthreads();
    return s_w[0] + s_w[1] + s_w[2];
}

extern "C" __global__ void __launch_bounds__(NT, 1)
gvae_kernel(const float* __restrict__ X, const int* __restrict__ EI, int E,
            const float* __restrict__ A,
            const float* __restrict__ W1, const float* __restrict__ B1,
            const float* __restrict__ G1, const float* __restrict__ BB1,
            const float* __restrict__ W2, const float* __restrict__ B2,
            const float* __restrict__ G2, const float* __restrict__ BB2,
            const float* __restrict__ MUW, const float* __restrict__ MUB,
            const float* __restrict__ LVW, const float* __restrict__ LVB,
            const float* __restrict__ D1W, const float* __restrict__ D1B,
            const float* __restrict__ D2W, const float* __restrict__ D2B,
            const float* __restrict__ EPS, float* __restrict__ OUT, int osz)
{
    const int bid = blockIdx.x, tid = threadIdx.x;
    __shared__ __align__(16) float s_x[NN];
    __shared__ __align__(16) float s_Bd[NN];
    __shared__ float s_An[NN];
    __shared__ float s_row[HID];
    __shared__ volatile float s_w[3];
    __shared__ float s_z[ZDIM];
    __shared__ int   s_nbr[NN + 8];
    __shared__ int   s_wcnt[3];
    __shared__ int   s_npad;

    Bar bar;
    asm volatile("ld.global.cg.s32 %0, [%1];" : "=r"(bar.base) : "l"(&g_flag[bid]));
    bar.ph = 0;

    // ---- stage 0: zero cnt row; init norm slots; zero M pad rows ----
    g_cnt[bid * NN + tid] = 0;
    if (bid == 0 && tid == 0) { g_norm[0] = 1.0f / (float)NN; g_norm[1] = 0.f; }
    if (bid == 0) g_M[NN * NN + tid] = 0.f;
    if (bid == 1) g_M[MSLOT + NN * NN + tid] = 0.f;
    gsync(bar);

    // ---- stage 1: scatter edges (int atomics = deterministic) + self loop;
    //      also rowmm1 (independent of graph structure) ----
    for (int e = bid * NT + tid; e < E; e += GRIDN * NT) {
        int s = EI[e], d = EI[E + e];
        atomicAdd(&g_cnt[d * NN + s], 1);
    }
    if (tid == 0) atomicAdd(&g_cnt[bid * NN + bid], 1);
    if (tid < INDIM) s_row[tid] = X[bid * INDIM + tid];
    __syncthreads();
    for (int f = tid; f < HID; f += NT) {
        float a0 = 0.f, a1 = 0.f;
        #pragma unroll 8
        for (int k = 0; k < INDIM; k += 2) {
            a0 += s_row[k]     * W1[k * HID + f];
            a1 += s_row[k + 1] * W1[(k + 1) * HID + f];
        }
        g_tmp1[bid * HID + f] = a0 + a1;
    }
    gsync(bar);

    // ---- stage 2: degree -> dis, degA ----
    {
        float dg = blk_sum((float)__ldcg(&g_cnt[bid * NN + tid]), s_w);
        float dA = blk_sum(A[bid * NN + tid], s_w);
        if (tid == 0) { g_dis[bid] = rsqrtf(dg); g_degA[bid] = dA; }
    }
    gsync(bar);

    // ---- stage 3: An row + agg1 ----
    {
        float db = __ldcg(&g_dis[bid]);
        s_An[tid] = db * __ldcg(&g_dis[tid]) * (float)__ldcg(&g_cnt[bid * NN + tid]);
    }
    __syncthreads();
    for (int f = tid; f < HID; f += NT) {
        float a0 = 0.f, a1 = 0.f;
        #pragma unroll 4
        for (int s = 0; s < NN; s += 2) {
            a0 += s_An[s]     * __ldcg(&g_tmp1[s * HID + f]);
            a1 += s_An[s + 1] * __ldcg(&g_tmp1[(s + 1) * HID + f]);
        }
        g_tmp2[bid * HID + f] = B1[f] + a0 + a1;
    }
    gsync(bar);

    // ---- stage 4: BN1 + relu (feature blocks) ----
    for (int f = bid; f < HID; f += GRIDN) {
        float v   = __ldcg(&g_tmp2[tid * HID + f]);
        float m   = blk_sum(v, s_w) * (1.0f / NN);
        float d   = v - m;
        float var = blk_sum(d * d, s_w) * (1.0f / NN);
        float sc  = G1[f] * rsqrtf(var + 1e-5f);
        g_h[tid * HID + f] = fmaxf(d * sc + BB1[f], 0.f);
    }
    gsync(bar);

    // ---- stage 5: rowmm2 ----
    for (int k = tid; k < HID; k += NT) s_row[k] = __ldcg(&g_h[bid * HID + k]);
    __syncthreads();
    for (int f = tid; f < HID; f += NT) {
        float a0 = 0.f, a1 = 0.f;
        #pragma unroll 8
        for (int k = 0; k < HID; k += 2) {
            a0 += s_row[k]     * W2[k * HID + f];
            a1 += s_row[k + 1] * W2[(k + 1) * HID + f];
        }
        g_tmp1[bid * HID + f] = a0 + a1;
    }
    gsync(bar);

    // ---- stage 6: agg2 ----
    for (int f = tid; f < HID; f += NT) {
        float a0 = 0.f, a1 = 0.f;
        #pragma unroll 4
        for (int s = 0; s < NN; s += 2) {
            a0 += s_An[s]     * __ldcg(&g_tmp1[s * HID + f]);
            a1 += s_An[s + 1] * __ldcg(&g_tmp1[(s + 1) * HID + f]);
        }
        g_tmp2[bid * HID + f] = B2[f] + a0 + a1;
    }
    gsync(bar);

    // ---- stage 7: BN2 + relu + fused sum-pool ----
    for (int f = bid; f < HID; f += GRIDN) {
        float v   = __ldcg(&g_tmp2[tid * HID + f]);
        float m   = blk_sum(v, s_w) * (1.0f / NN);
        float d   = v - m;
        float var = blk_sum(d * d, s_w) * (1.0f / NN);
        float sc  = G2[f] * rsqrtf(var + 1e-5f);
        float hv  = fmaxf(d * sc + BB2[f], 0.f);
        g_h[tid * HID + f] = hv;
        float ps = blk_sum(hv, s_w);
        if (tid == 0) g_gvec[f] = ps;
    }
    gsync(bar);

    // ---- stage 8: VAE head + dec1 (block 0) ----
    if (bid == 0) {
        for (int k = tid; k < HID; k += NT) s_row[k] = __ldcg(&g_gvec[k]);
        __syncthreads();
        float klt = 0.f;
        if (tid < ZDIM) {
            float mu = MUB[tid], lv = LVB[tid];
            #pragma unroll 8
            for (int k = 0; k < HID; k++) {
                float gv = s_row[k];
                mu += gv * MUW[k * ZDIM + tid];
                lv += gv * LVW[k * ZDIM + tid];
            }
            s_z[tid] = mu + EPS[tid] * expf(0.5f * lv);
            klt = 1.f + lv - mu * mu - expf(lv);
        }
        float ks = blk_sum(klt, s_w);
        if (tid == 0) g_kl = -0.5f * ks * (1.0f / ZDIM);
        __syncthreads();
        for (int f = tid; f < HID; f += NT) {
            float acc = D1B[f];
            #pragma unroll
            for (int k = 0; k < ZDIM; k++) acc += s_z[k] * D1W[k * HID + f];
            g_d1[f] = fmaxf(acc, 0.f);
        }
    }
    gsync(bar);

    // ---- stage 9: dec2 (balanced: ~49 outputs per block) ----
    for (int k = tid; k < HID; k += NT) s_row[k] = __ldcg(&g_d1[k]);
    __syncthreads();
    {
        int per = (TRIN + GRIDN - 1) / GRIDN;   // 49
        int o = bid * per + tid;
        if (tid < per && o < TRIN) {
            float a0 = 0.f, a1 = 0.f, a2 = 0.f, a3 = 0.f;
            #pragma unroll 4
            for (int k = 0; k < HID; k += 4) {
                a0 += s_row[k]     * D2W[k * TRIN + o];
                a1 += s_row[k + 1] * D2W[(k + 1) * TRIN + o];
                a2 += s_row[k + 2] * D2W[(k + 2) * TRIN + o];
                a3 += s_row[k + 3] * D2W[(k + 3) * TRIN + o];
            }
            g_vecb[o] = D2B[o] + ((a0 + a1) + (a2 + a3));
        }
    }
    gsync(bar);

    // ---- stage 10: build B, Bd, degB, BCE partials ----
    {
        int i_ = bid < tid ? bid : tid;
        int j_ = bid < tid ? tid : bid;
        int o  = i_ * NN - (i_ * (i_ - 1)) / 2 + (j_ - i_);
        float v  = __ldcg(&g_vecb[o]);
        float Bv = 1.f / (1.f + expf(-v));
        g_B[bid * NN + tid] = Bv;
        if (tid == bid) g_Bd[bid] = Bv;
        float rc = 0.f;
        if (tid >= bid) {
            float truth = A[bid * NN + tid];
            rc = fmaxf(v, 0.f) - v * truth + log1pf(expf(-fabsf(v)));
        }
        float dB = blk_sum(Bv, s_w);
        float rs = blk_sum(rc, s_w);
        if (tid == 0) { g_degB[bid] = dB; g_recpart[bid] = rs; }
    }
    gsync(bar);

    // ---- MPM setup: Q row -> float4 registers, D value, neighbor list ----
    s_Bd[tid] = __ldcg(&g_Bd[tid]);
    {
        bool pred = (tid != bid) && (A[bid * NN + tid] != 0.f);
        unsigned mm = __ballot_sync(0xFFFFFFFFu, pred);
        int w = tid >> 5, lane = tid & 31;
        if (lane == 0) s_wcnt[w] = __popc(mm);
        __syncthreads();
        int base = 0;
        if (w > 0) base += s_wcnt[0];
        if (w > 1) base += s_wcnt[1];
        if (pred) s_nbr[base + __popc(mm & ((1u << lane) - 1u))] = tid;
        __syncthreads();
        if (tid == 0) {
            int c = s_wcnt[0] + s_wcnt[1] + s_wcnt[2];
            while (c & 7) s_nbr[c++] = NN;       // pad -> zero row of M
            s_npad = c;
        }
    }
    __syncthreads();
    const int nn8 = s_npad;

    float4 q4[24];
    float  Da;
    {
        float Bda = s_Bd[tid];
        Da = A[bid * NN + bid] * Bda /
             (fabsf(__ldcg(&g_degA[bid]) - __ldcg(&g_degB[tid])) + 1.f);
        const float4* br  = reinterpret_cast<const float4*>(g_B + tid * NN);
        const float4* sd4 = reinterpret_cast<const float4*>(s_Bd);
        #pragma unroll
        for (int b4 = 0; b4 < 24; b4++) {
            float4 bv = __ldcg(&br[b4]);
            float4 sd = sd4[b4];
            int b = 4 * b4;
            float4 qv;
            qv.x = (b + 0 == tid) ? 0.f : bv.x * Bda * sd.x;
            qv.y = (b + 1 == tid) ? 0.f : bv.y * Bda * sd.y;
            qv.z = (b + 2 == tid) ? 0.f : bv.z * Bda * sd.z;
            qv.w = (b + 3 == tid) ? 0.f : bv.w * Bda * sd.w;
            q4[b4] = qv;
        }
        s_x[tid] = 1.0f / (float)NN;
    }
    __syncthreads();

    // ---- MPM loop: 1 barrier/iter; scalar-RED norm with 3-slot rotation ----
    for (int k = 0; k < ITERS; k++) {
        float* Mb = g_M + (k & 1) * MSLOT;
        // phase A: M[bid, tid] = max_b q[tid][b] * x[bid][b]
        {
            const float4* sx4 = reinterpret_cast<const float4*>(s_x);
            float m0 = 0.f, m1 = 0.f, m2 = 0.f, m3 = 0.f;
            #pragma unroll
            for (int b4 = 0; b4 < 24; b4++) {
                float4 xv = sx4[b4];
                float4 qv = q4[b4];
                m0 = fmaxf(m0, qv.x * xv.x);
                m1 = fmaxf(m1, qv.y * xv.y);
                m2 = fmaxf(m2, qv.z * xv.z);
                m3 = fmaxf(m3, qv.w * xv.w);
            }
            Mb[bid * NN + tid] = fmaxf(fmaxf(m0, m1), fmaxf(m2, m3));
        }
        gsync(bar);
        // phase B
        float invn = rsqrtf(__ldcg(&g_norm[k % 3]));
        float msg = 0.f;
        for (int j = 0; j < nn8; j += 8) {
            float t0 = __ldcg(&Mb[s_nbr[j + 0] * NN + tid]);
            float t1 = __ldcg(&Mb[s_nbr[j + 1] * NN + tid]);
            float t2 = __ldcg(&Mb[s_nbr[j + 2] * NN + tid]);
            float t3 = __ldcg(&Mb[s_nbr[j + 3] * NN + tid]);
            float t4 = __ldcg(&Mb[s_nbr[j + 4] * NN + tid]);
            float t5 = __ldcg(&Mb[s_nbr[j + 5] * NN + tid]);
            float t6 = __ldcg(&Mb[s_nbr[j + 6] * NN + tid]);
            float t7 = __ldcg(&Mb[s_nbr[j + 7] * NN + tid]);
            msg += ((t0 + t1) + (t2 + t3)) + ((t4 + t5) + (t6 + t7));
        }
        float xn = (s_x[tid] * Da + msg) * invn;
        float p = xn * xn;
        #pragma unroll
        for (int o = 16; o; o >>= 1) p += __shfl_down_sync(0xFFFFFFFFu, p, o);
        if ((tid & 31) == 0) atomicAdd(&g_norm[(k + 1) % 3], p);
        if (tid == 0) *(volatile float*)&g_norm[(k + 2) % 3] = 0.f;
        s_x[tid] = xn;
        __syncthreads();
    }
    gsync(bar);

    // ---- final normalize + outputs ----
    {
        float invn = rsqrtf(__ldcg(&g_norm[ITERS % 3]));
        int off = (osz > NN * NN) ? (osz - NN * NN) : 0;
        if (osz >= NN * NN)
            OUT[off + bid * NN + tid] = s_x[tid] * invn;
        if (bid == 0) {
            float rs = blk_sum(__ldcg(&g_recpart[tid]), s_w);
            if (tid == 0 && (osz < NN * NN || off > 0))
                OUT[0] = rs * (1.0f / (float)TRIN) + __ldcg(&g_kl);
        }
    }
}

extern "C" void kernel_launch(void* const* d_in, const int* in_sizes, int n_in,
                              void* d_out, int out_size) {
    const float* X   = (const float*)d_in[0];
    const int*   EI  = (const int*)  d_in[1];
    const float* A   = (const float*)d_in[3];
    const float* W1  = (const float*)d_in[4];
    const float* B1  = (const float*)d_in[5];
    const float* G1  = (const float*)d_in[6];
    const float* BB1 = (const float*)d_in[7];
    const float* W2  = (const float*)d_in[8];
    const float* B2  = (const float*)d_in[9];
    const float* G2  = (const float*)d_in[10];
    const float* BB2 = (const float*)d_in[11];
    const float* MUW = (const float*)d_in[12];
    const float* MUB = (const float*)d_in[13];
    const float* LVW = (const float*)d_in[14];
    const float* LVB = (const float*)d_in[15];
    const float* D1W = (const float*)d_in[16];
    const float* D1B = (const float*)d_in[17];
    const float* D2W = (const float*)d_in[18];
    const float* D2B = (const float*)d_in[19];
    const float* EPS = (const float*)d_in[20];
    int E = in_sizes[1] / 2;

    gvae_kernel<<<GRIDN, NT>>>(X, EI, E, A, W1, B1, G1, BB1, W2, B2, G2, BB2,
                               MUW, MUB, LVW, LVB, D1W, D1B, D2W, D2B, EPS,
                               (float*)d_out, out_size);
}

// round 4
// speedup vs baseline: 1.6639x; 1.6639x over previous
#include <cuda_runtime.h>
#include <math.h>

#define NN    96
#define INDIM 64
#define HID   256
#define ZDIM  64
#define TRIN  4656
#define GRIDN 96
#define NT    128
#define ITERS 50
#define RENORM 5
#define NSLOT (ITERS / RENORM)         // 10 renorm partial slots
#define MSLOT ((NN + 1) * NN)          // 97 rows; row 96 = zero pad
#define F0    11                       // front-end flag bumps

// ------------- persistent device scratch (no allocations allowed) -------------
__device__ int   g_flag[GRIDN];        // per-block monotonic progress counters
__device__ int   g_cnt[NN * NN];
__device__ float g_dis[NN];
__device__ float g_degA[NN];
__device__ float g_tmp1[NN * HID];
__device__ float g_tmp2[NN * HID];
__device__ float g_h[NN * HID];
__device__ float g_gvec[HID];
__device__ float g_d1[HID];
__device__ float g_kl;
__device__ float g_vecb[TRIN];
__device__ float g_B[NN * NN];
__device__ float g_Bd[NN];
__device__ float g_degB[NN];
__device__ float g_recpart[NN];
__device__ float g_part[NSLOT * NN];   // disjoint slot per renorm -> no WAR
__device__ float g_M[2 * MSLOT];       // ping-pong max-message matrix (+pad row)

// ---- release/acquire flag primitives (NO atomics anywhere) ----
__device__ __forceinline__ int ld_acq(const int* p) {
    int v; asm volatile("ld.acquire.gpu.global.s32 %0, [%1];" : "=r"(v) : "l"(p)); return v;
}
__device__ __forceinline__ void st_rel(int* p, int v) {
    asm volatile("st.release.gpu.global.s32 [%0], %1;" :: "l"(p), "r"(v) : "memory");
}

// global wait: warp 0 polls all 96 flags (3 per lane), others idle at bar
__device__ __forceinline__ void wait_all(int tgt) {
    if (threadIdx.x < 32) {
        for (;;) {
            int ok = 1;
            #pragma unroll
            for (int i = 0; i < 3; i++)
                ok &= (ld_acq(&g_flag[threadIdx.x + 32 * i]) >= tgt);
            if (__all_sync(0xFFFFFFFFu, ok)) break;
        }
    }
    __syncthreads();
}

// neighbor-only wait: warp 0 polls nnb neighbor flags
__device__ __forceinline__ void wait_nbr(const int* s_nbr, int nnb, int tgt) {
    if (threadIdx.x < 32) {
        for (;;) {
            int ok = 1;
            for (int i = threadIdx.x; i < nnb; i += 32)
                ok &= (ld_acq(&g_flag[s_nbr[i]]) >= tgt);
            if (__all_sync(0xFFFFFFFFu, ok)) break;
        }
    }
    __syncthreads();
}

// full global barrier (bump own flag + wait all)
__device__ __forceinline__ void gbar(int base, int& ph) {
    int tgt = base + (++ph);
    __syncthreads();                           // all block threads' work done
    if (threadIdx.x == 0) st_rel(&g_flag[blockIdx.x], tgt);
    wait_all(tgt);
}

__device__ __forceinline__ float blk_sum(float v, volatile float* s_w) {
    __syncthreads();
    #pragma unroll
    for (int o = 16; o; o >>= 1) v += __shfl_down_sync(0xFFFFFFFFu, v, o);
    if ((threadIdx.x & 31) == 0) s_w[threadIdx.x >> 5] = v;
    __syncthreads();
    return (s_w[0] + s_w[1]) + (s_w[2] + s_w[3]);
}

extern "C" __global__ void __launch_bounds__(NT, 1)
gvae_kernel(const float* __restrict__ X, const int* __restrict__ EI, int E,
            const float* __restrict__ A,
            const float* __restrict__ W1, const float* __restrict__ B1,
            const float* __restrict__ G1, const float* __restrict__ BB1,
            const float* __restrict__ W2, const float* __restrict__ B2,
            const float* __restrict__ G2, const float* __restrict__ BB2,
            const float* __restrict__ MUW, const float* __restrict__ MUB,
            const float* __restrict__ LVW, const float* __restrict__ LVB,
            const float* __restrict__ D1W, const float* __restrict__ D1B,
            const float* __restrict__ D2W, const float* __restrict__ D2B,
            const float* __restrict__ EPS, float* __restrict__ OUT, int osz)
{
    const int bid = blockIdx.x, tid = threadIdx.x;
    __shared__ __align__(16) float s_x[NN];
    __shared__ __align__(16) float s_Bd[NN];
    __shared__ float s_An[NN];
    __shared__ float s_row[HID];
    __shared__ volatile float s_w[4];
    __shared__ float s_z[ZDIM];
    __shared__ int   s_nbr[NN + 8];
    __shared__ int   s_wcnt[4];
    __shared__ int   s_cnt2[2];

    int base = ld_acq(&g_flag[bid]);   // equal across blocks (uniform bump count/launch)
    int ph = 0;

    // ---- stage 0: zero cnt row; zero M pad rows ----
    if (tid < NN) g_cnt[bid * NN + tid] = 0;
    if (bid == 0 && tid < NN) g_M[NN * NN + tid] = 0.f;
    if (bid == 1 && tid < NN) g_M[MSLOT + NN * NN + tid] = 0.f;
    gbar(base, ph);                                              // 1

    // ---- stage 1: scatter edges (int atomics, scattered addrs) + rowmm1 ----
    for (int e = bid * NT + tid; e < E; e += GRIDN * NT) {
        int s = EI[e], d = EI[E + e];
        atomicAdd(&g_cnt[d * NN + s], 1);
    }
    if (tid == 0) atomicAdd(&g_cnt[bid * NN + bid], 1);
    if (tid < INDIM) s_row[tid] = X[bid * INDIM + tid];
    __syncthreads();
    for (int f = tid; f < HID; f += NT) {
        float a0 = 0.f, a1 = 0.f;
        #pragma unroll 8
        for (int k = 0; k < INDIM; k += 2) {
            a0 += s_row[k]     * W1[k * HID + f];
            a1 += s_row[k + 1] * W1[(k + 1) * HID + f];
        }
        g_tmp1[bid * HID + f] = a0 + a1;
    }
    gbar(base, ph);                                              // 2

    // ---- stage 2: degree -> dis, degA ----
    {
        float dg = blk_sum((tid < NN) ? (float)__ldcg(&g_cnt[bid * NN + tid]) : 0.f, s_w);
        float dA = blk_sum((tid < NN) ? A[bid * NN + tid] : 0.f, s_w);
        if (tid == 0) { g_dis[bid] = rsqrtf(dg); g_degA[bid] = dA; }
    }
    gbar(base, ph);                                              // 3

    // ---- stage 3: An row + agg1 ----
    {
        float db = __ldcg(&g_dis[bid]);
        if (tid < NN)
            s_An[tid] = db * __ldcg(&g_dis[tid]) * (float)__ldcg(&g_cnt[bid * NN + tid]);
    }
    __syncthreads();
    for (int f = tid; f < HID; f += NT) {
        float a0 = 0.f, a1 = 0.f;
        #pragma unroll 4
        for (int s = 0; s < NN; s += 2) {
            a0 += s_An[s]     * __ldcg(&g_tmp1[s * HID + f]);
            a1 += s_An[s + 1] * __ldcg(&g_tmp1[(s + 1) * HID + f]);
        }
        g_tmp2[bid * HID + f] = B1[f] + a0 + a1;
    }
    gbar(base, ph);                                              // 4

    // ---- stage 4: BN1 + relu ----
    for (int f = bid; f < HID; f += GRIDN) {
        float v   = (tid < NN) ? __ldcg(&g_tmp2[tid * HID + f]) : 0.f;
        float m   = blk_sum(v, s_w) * (1.0f / NN);
        float d   = (tid < NN) ? v - m : 0.f;
        float var = blk_sum(d * d, s_w) * (1.0f / NN);
        float sc  = G1[f] * rsqrtf(var + 1e-5f);
        if (tid < NN) g_h[tid * HID + f] = fmaxf(d * sc + BB1[f], 0.f);
    }
    gbar(base, ph);                                              // 5

    // ---- stage 5: rowmm2 ----
    for (int k = tid; k < HID; k += NT) s_row[k] = __ldcg(&g_h[bid * HID + k]);
    __syncthreads();
    for (int f = tid; f < HID; f += NT) {
        float a0 = 0.f, a1 = 0.f;
        #pragma unroll 8
        for (int k = 0; k < HID; k += 2) {
            a0 += s_row[k]     * W2[k * HID + f];
            a1 += s_row[k + 1] * W2[(k + 1) * HID + f];
        }
        g_tmp1[bid * HID + f] = a0 + a1;
    }
    gbar(base, ph);                                              // 6

    // ---- stage 6: agg2 ----
    for (int f = tid; f < HID; f += NT) {
        float a0 = 0.f, a1 = 0.f;
        #pragma unroll 4
        for (int s = 0; s < NN; s += 2) {
            a0 += s_An[s]     * __ldcg(&g_tmp1[s * HID + f]);
            a1 += s_An[s + 1] * __ldcg(&g_tmp1[(s + 1) * HID + f]);
        }
        g_tmp2[bid * HID + f] = B2[f] + a0 + a1;
    }
    gbar(base, ph);                                              // 7

    // ---- stage 7: BN2 + relu + fused sum-pool ----
    for (int f = bid; f < HID; f += GRIDN) {
        float v   = (tid < NN) ? __ldcg(&g_tmp2[tid * HID + f]) : 0.f;
        float m   = blk_sum(v, s_w) * (1.0f / NN);
        float d   = (tid < NN) ? v - m : 0.f;
        float var = blk_sum(d * d, s_w) * (1.0f / NN);
        float sc  = G2[f] * rsqrtf(var + 1e-5f);
        float hv  = (tid < NN) ? fmaxf(d * sc + BB2[f], 0.f) : 0.f;
        if (tid < NN) g_h[tid * HID + f] = hv;
        float ps = blk_sum(hv, s_w);
        if (tid == 0) g_gvec[f] = ps;
    }
    gbar(base, ph);                                              // 8

    // ---- stage 8: VAE head + dec1 (block 0) ----
    if (bid == 0) {
        for (int k = tid; k < HID; k += NT) s_row[k] = __ldcg(&g_gvec[k]);
        __syncthreads();
        float klt = 0.f;
        if (tid < ZDIM) {
            float mu = MUB[tid], lv = LVB[tid];
            #pragma unroll 8
            for (int k = 0; k < HID; k++) {
                float gv = s_row[k];
                mu += gv * MUW[k * ZDIM + tid];
                lv += gv * LVW[k * ZDIM + tid];
            }
            s_z[tid] = mu + EPS[tid] * expf(0.5f * lv);
            klt = 1.f + lv - mu * mu - expf(lv);
        }
        float ks = blk_sum(klt, s_w);
        if (tid == 0) g_kl = -0.5f * ks * (1.0f / ZDIM);
        __syncthreads();
        for (int f = tid; f < HID; f += NT) {
            float acc = D1B[f];
            #pragma unroll
            for (int k = 0; k < ZDIM; k++) acc += s_z[k] * D1W[k * HID + f];
            g_d1[f] = fmaxf(acc, 0.f);
        }
    }
    gbar(base, ph);                                              // 9

    // ---- stage 9: dec2 (balanced ~49 outputs/block) ----
    for (int k = tid; k < HID; k += NT) s_row[k] = __ldcg(&g_d1[k]);
    __syncthreads();
    {
        const int per = (TRIN + GRIDN - 1) / GRIDN;  // 49
        int o = bid * per + tid;
        if (tid < per && o < TRIN) {
            float a0 = 0.f, a1 = 0.f, a2 = 0.f, a3 = 0.f;
            #pragma unroll 4
            for (int k = 0; k < HID; k += 4) {
                a0 += s_row[k]     * D2W[k * TRIN + o];
                a1 += s_row[k + 1] * D2W[(k + 1) * TRIN + o];
                a2 += s_row[k + 2] * D2W[(k + 2) * TRIN + o];
                a3 += s_row[k + 3] * D2W[(k + 3) * TRIN + o];
            }
            g_vecb[o] = D2B[o] + ((a0 + a1) + (a2 + a3));
        }
    }
    gbar(base, ph);                                              // 10

    // ---- stage 10: build B, Bd, degB, BCE partials ----
    {
        float Bv = 0.f, rc = 0.f;
        if (tid < NN) {
            int i_ = bid < tid ? bid : tid;
            int j_ = bid < tid ? tid : bid;
            int o  = i_ * NN - (i_ * (i_ - 1)) / 2 + (j_ - i_);
            float v = __ldcg(&g_vecb[o]);
            Bv = 1.f / (1.f + expf(-v));
            g_B[bid * NN + tid] = Bv;
            if (tid == bid) g_Bd[bid] = Bv;
            if (tid >= bid) {
                float truth = A[bid * NN + tid];
                rc = fmaxf(v, 0.f) - v * truth + log1pf(expf(-fabsf(v)));
            }
        }
        float dB = blk_sum(Bv, s_w);
        float rs = blk_sum(rc, s_w);
        if (tid == 0) { g_degB[bid] = dB; g_recpart[bid] = rs; }
    }
    gbar(base, ph);                                              // 11  (== F0)

    // ---- MPM setup: Q row -> float4 regs, D value, neighbor list ----
    if (tid < NN) s_Bd[tid] = __ldcg(&g_Bd[tid]);
    {
        bool pred = (tid < NN) && (tid != bid) && (A[bid * NN + tid] != 0.f);
        unsigned mm = __ballot_sync(0xFFFFFFFFu, pred);
        int w = tid >> 5, lane = tid & 31;
        if (lane == 0) s_wcnt[w] = __popc(mm);
        __syncthreads();
        int bpos = 0;
        if (w > 0) bpos += s_wcnt[0];
        if (w > 1) bpos += s_wcnt[1];
        if (w > 2) bpos += s_wcnt[2];
        if (pred) s_nbr[bpos + __popc(mm & ((1u << lane) - 1u))] = tid;
        __syncthreads();
        if (tid == 0) {
            int c = s_wcnt[0] + s_wcnt[1] + s_wcnt[2] + s_wcnt[3];
            s_cnt2[0] = c;
            while (c & 7) s_nbr[c++] = NN;       // pad -> zero row of M
            s_cnt2[1] = c;
        }
    }
    __syncthreads();
    const int nnb = s_cnt2[0];
    const int nn8 = s_cnt2[1];

    float4 q4[24];
    float  Da = 0.f;
    if (tid < NN) {
        float Bda = s_Bd[tid];
        Da = A[bid * NN + bid] * Bda /
             (fabsf(__ldcg(&g_degA[bid]) - __ldcg(&g_degB[tid])) + 1.f);
        const float4* br  = reinterpret_cast<const float4*>(g_B + tid * NN);
        const float4* sd4 = reinterpret_cast<const float4*>(s_Bd);
        #pragma unroll
        for (int b4 = 0; b4 < 24; b4++) {
            float4 bv = __ldcg(&br[b4]);
            float4 sd = sd4[b4];
            int b = 4 * b4;
            float4 qv;
            qv.x = (b + 0 == tid) ? 0.f : bv.x * Bda * sd.x;
            qv.y = (b + 1 == tid) ? 0.f : bv.y * Bda * sd.y;
            qv.z = (b + 2 == tid) ? 0.f : bv.z * Bda * sd.z;
            qv.w = (b + 3 == tid) ? 0.f : bv.w * Bda * sd.w;
            q4[b4] = qv;
        }
        s_x[tid] = 1.0f / (float)NN;
    }
    __syncthreads();

    // ---- MPM: unnormalized iteration, neighbor-only sync, renorm every 5 ----
    for (int k = 0; k < ITERS; k++) {
        float* Mb = g_M + (k & 1) * MSLOT;
        // phase A: M[bid, tid] = max_b q[tid][b] * x[bid][b]
        if (tid < NN) {
            const float4* sx4 = reinterpret_cast<const float4*>(s_x);
            float m0 = 0.f, m1 = 0.f, m2 = 0.f, m3 = 0.f;
            #pragma unroll
            for (int b4 = 0; b4 < 24; b4++) {
                float4 xv = sx4[b4];
                float4 qv = q4[b4];
                m0 = fmaxf(m0, qv.x * xv.x);
                m1 = fmaxf(m1, qv.y * xv.y);
                m2 = fmaxf(m2, qv.z * xv.z);
                m3 = fmaxf(m3, qv.w * xv.w);
            }
            Mb[bid * NN + tid] = fmaxf(fmaxf(m0, m1), fmaxf(m2, m3));
        }
        __syncthreads();
        int tgtA = base + (++ph);
        if (tid == 0) st_rel(&g_flag[bid], tgtA);
        wait_nbr(s_nbr, nnb, tgtA);

        // phase B: gather neighbor maxima
        float xn = 0.f;
        if (tid < NN) {
            float msg = 0.f;
            for (int j = 0; j < nn8; j += 8) {
                float t0 = __ldcg(&Mb[s_nbr[j + 0] * NN + tid]);
                float t1 = __ldcg(&Mb[s_nbr[j + 1] * NN + tid]);
                float t2 = __ldcg(&Mb[s_nbr[j + 2] * NN + tid]);
                float t3 = __ldcg(&Mb[s_nbr[j + 3] * NN + tid]);
                float t4 = __ldcg(&Mb[s_nbr[j + 4] * NN + tid]);
                float t5 = __ldcg(&Mb[s_nbr[j + 5] * NN + tid]);
                float t6 = __ldcg(&Mb[s_nbr[j + 6] * NN + tid]);
                float t7 = __ldcg(&Mb[s_nbr[j + 7] * NN + tid]);
                msg += ((t0 + t1) + (t2 + t3)) + ((t4 + t5) + (t6 + t7));
            }
            xn = s_x[tid] * Da + msg;
        }
        const bool rn = ((k + 1) % RENORM == 0);
        const int  r  = k / RENORM;
        if (rn) {
            float p = blk_sum(xn * xn, s_w);
            if (tid == 0) g_part[r * NN + bid] = p;
        }
        __syncthreads();                         // Mb loads + g_part done before bump
        int tgtB = base + (++ph);
        if (tid == 0) st_rel(&g_flag[bid], tgtB);

        if (rn) {
            wait_all(tgtB);
            float pv   = (tid < NN) ? __ldcg(&g_part[r * NN + tid]) : 0.f;
            float invn = rsqrtf(blk_sum(pv, s_w));
            if (k == ITERS - 1) {
                // final normalize + outputs
                int off = (osz > NN * NN) ? (osz - NN * NN) : 0;
                if (osz >= NN * NN && tid < NN)
                    OUT[off + bid * NN + tid] = xn * invn;
                if (bid == 0) {
                    float rp = (tid < NN) ? __ldcg(&g_recpart[tid]) : 0.f;
                    float rs = blk_sum(rp, s_w);
                    if (tid == 0 && (osz < NN * NN || off > 0))
                        OUT[0] = rs * (1.0f / (float)TRIN) + __ldcg(&g_kl);
                }
                return;
            }
            if (tid < NN) xn *= invn;
        }
        if (tid < NN) s_x[tid] = xn;
        __syncthreads();
    }
}

extern "C" void kernel_launch(void* const* d_in, const int* in_sizes, int n_in,
                              void* d_out, int out_size) {
    const float* X   = (const float*)d_in[0];
    const int*   EI  = (const int*)  d_in[1];
    const float* A   = (const float*)d_in[3];
    const float* W1  = (const float*)d_in[4];
    const float* B1  = (const float*)d_in[5];
    const float* G1  = (const float*)d_in[6];
    const float* BB1 = (const float*)d_in[7];
    const float* W2  = (const float*)d_in[8];
    const float* B2  = (const float*)d_in[9];
    const float* G2  = (const float*)d_in[10];
    const float* BB2 = (const float*)d_in[11];
    const float* MUW = (const float*)d_in[12];
    const float* MUB = (const float*)d_in[13];
    const float* LVW = (const float*)d_in[14];
    const float* LVB = (const float*)d_in[15];
    const float* D1W = (const float*)d_in[16];
    const float* D1B = (const float*)d_in[17];
    const float* D2W = (const float*)d_in[18];
    const float* D2B = (const float*)d_in[19];
    const float* EPS = (const float*)d_in[20];
    int E = in_sizes[1] / 2;

    gvae_kernel<<<GRIDN, NT>>>(X, EI, E, A, W1, B1, G1, BB1, W2, B2, G2, BB2,
                               MUW, MUB, LVW, LVB, D1W, D1B, D2W, D2B, EPS,
                               (float*)d_out, out_size);
}